// round 14
// baseline (speedup 1.0000x reference)
#include <cuda_runtime.h>

// Live computation: out = MLP( (mean_p lidar[b,p,:]) @ wv ).
// Attention is dead (zero-pad last query row -> uniform softmax -> mean of V).
//
// 3-kernel chain, R6-exact bodies, chained with PDL (programmatic dependent
// launch): K2/K3 blocks pre-launch into spare SM slots, prefetch their
// weights into L2 pre-sync, then HW-wait at cudaGridDependencySynchronize()
// until the predecessor grid completes. Kills the two launch gaps without
// software spinning (which failed 4x).

#define BATCH     16
#define N_POINTS  4096
#define LIDAR_C   256
#define C4        (LIDAR_C / 4)           // 64
#define D_MODEL   1024
#define H1        128
#define SPLIT     64
#define PTS_PER_BLK (N_POINTS / SPLIT)    // 64

__device__ float4 g_partial[SPLIT * BATCH * C4];   // [64][16][64] f4 = 1 MB
__device__ float4 g_h1p[BATCH * 8 * (H1 / 4)];     // [16][8][32] f4

__device__ __forceinline__ void prefetch_l2(const void* p) {
    asm volatile("prefetch.global.L2 [%0];" :: "l"(p));
}

// ---------------------------------------------------------------------------
// K1: partial column sums of lidar (DRAM-bound, 67 MB). R6-exact. FROZEN.
// ---------------------------------------------------------------------------
__global__ void __launch_bounds__(256)
lidar_reduce_kernel(const float4* __restrict__ lidar4)
{
    const int b  = blockIdx.x;
    const int s  = blockIdx.y;
    const int c4 = threadIdx.x & 63;
    const int r  = threadIdx.x >> 6;

    const float4* base = lidar4
        + ((size_t)b * N_POINTS + (size_t)s * PTS_PER_BLK + (size_t)r * 16) * C4 + c4;

    float4 acc = make_float4(0.f, 0.f, 0.f, 0.f);
#pragma unroll
    for (int i = 0; i < 16; ++i) {
        float4 v = __ldcs(&base[(size_t)i * C4]);
        acc.x += v.x; acc.y += v.y; acc.z += v.z; acc.w += v.w;
    }

    __shared__ float4 sp[4][C4];
    sp[r][c4] = acc;
    __syncthreads();

    if (r == 0) {
        float4 a = sp[0][c4], bb = sp[1][c4], c = sp[2][c4], d = sp[3][c4];
        float4 t;
        t.x = (a.x + bb.x) + (c.x + d.x);
        t.y = (a.y + bb.y) + (c.y + d.y);
        t.z = (a.z + bb.z) + (c.z + d.z);
        t.w = (a.w + bb.w) + (c.w + d.w);
        g_partial[((size_t)s * BATCH + b) * C4 + c4] = t;
    }
}

// ---------------------------------------------------------------------------
// K2: per (batch, j-chunk): fold partials -> mean; bins_chunk = mean @ wv
// cols [jq*128,+128); h1 partial = bins_chunk @ wo1[chunk rows]. R6 body,
// preceded by a pre-sync L2 prefetch of this block's weight slices.
// ---------------------------------------------------------------------------
__global__ void __launch_bounds__(256)
bins_h1_kernel(const float4* __restrict__ wv4,     // [256][256] f4
               const float4* __restrict__ wo14)    // [1024][32] f4
{
    const int b   = blockIdx.x;
    const int jq  = blockIdx.y;                    // 0..7
    const int tid = threadIdx.x;
    const int j4  = tid & 31;
    const int kg  = tid >> 5;                      // 0..7

    // ---- pre-sync preamble: warm L2 with this block's weights -------------
    // (independent of K1's output; runs while waiting for K1 via PDL)
    {
        const float4* wvb = wv4 + (size_t)jq * 32;          // cols jq*32..+32
        prefetch_l2(wvb + (size_t)tid * 256 + 0);
        prefetch_l2(wvb + (size_t)tid * 256 + 8);
        prefetch_l2(wvb + (size_t)tid * 256 + 16);
        prefetch_l2(wvb + (size_t)tid * 256 + 24);
        const float4* w1b = wo14 + (size_t)jq * 128 * 32;   // 64 KB slice
        prefetch_l2(w1b + (size_t)tid * 16);
        prefetch_l2(w1b + (size_t)tid * 16 + 8);
    }

#if __CUDA_ARCH__ >= 900
    cudaGridDependencySynchronize();
#endif

    __shared__ float4 sp[4][C4];
    __shared__ float  s_mean[LIDAR_C];
    __shared__ float  s_binsc[128];
    __shared__ float4 s_red[8][32];

    // ---- fold 64 partials -> mean -----------------------------------------
    {
        const int c4 = tid & 63;
        const int sg = tid >> 6;                   // 0..3
        const float4* p = g_partial + (size_t)b * C4 + c4;
        float4 acc = make_float4(0.f, 0.f, 0.f, 0.f);
#pragma unroll
        for (int i = 0; i < 16; ++i) {
            float4 v = p[(size_t)(sg * 16 + i) * (BATCH * C4)];
            acc.x += v.x; acc.y += v.y; acc.z += v.z; acc.w += v.w;
        }
        sp[sg][c4] = acc;
    }
    __syncthreads();
    if (tid < C4) {
        float4 a = sp[0][tid], bb = sp[1][tid], c = sp[2][tid], d = sp[3][tid];
        const float inv = 1.0f / (float)N_POINTS;
        s_mean[tid * 4 + 0] = ((a.x + bb.x) + (c.x + d.x)) * inv;
        s_mean[tid * 4 + 1] = ((a.y + bb.y) + (c.y + d.y)) * inv;
        s_mean[tid * 4 + 2] = ((a.z + bb.z) + (c.z + d.z)) * inv;
        s_mean[tid * 4 + 3] = ((a.w + bb.w) + (c.w + d.w)) * inv;
    }
    __syncthreads();

    // ---- bins chunk: 32 j4 x 8 kg of 32 k ----------------------------------
    {
        const float4* w = wv4 + (size_t)(kg * 32) * 256 + jq * 32 + j4;
        const float*  m = s_mean + kg * 32;
        float4 acc = make_float4(0.f, 0.f, 0.f, 0.f);
#pragma unroll 8
        for (int k = 0; k < 32; ++k) {
            float4 v = __ldg(&w[(size_t)k * 256]);
            float  s = m[k];
            acc.x += s * v.x; acc.y += s * v.y; acc.z += s * v.z; acc.w += s * v.w;
        }
        s_red[kg][j4] = acc;
    }
    __syncthreads();
    if (tid < 32) {
        float4 acc = make_float4(0.f, 0.f, 0.f, 0.f);
#pragma unroll
        for (int g = 0; g < 8; ++g) {
            float4 v = s_red[g][tid];
            acc.x += v.x; acc.y += v.y; acc.z += v.z; acc.w += v.w;
        }
        s_binsc[tid * 4 + 0] = acc.x;
        s_binsc[tid * 4 + 1] = acc.y;
        s_binsc[tid * 4 + 2] = acc.z;
        s_binsc[tid * 4 + 3] = acc.w;
    }
    __syncthreads();

    // ---- h1 partial: 32 j4 x 8 kg of 16 k ----------------------------------
    {
        const float4* w = wo14 + ((size_t)jq * 128 + kg * 16) * 32 + j4;
        const float*  m = s_binsc + kg * 16;
        float4 acc = make_float4(0.f, 0.f, 0.f, 0.f);
#pragma unroll
        for (int k = 0; k < 16; ++k) {
            float4 v = __ldg(&w[(size_t)k * 32]);
            float  s = m[k];
            acc.x += s * v.x; acc.y += s * v.y; acc.z += s * v.z; acc.w += s * v.w;
        }
        __syncthreads();
        s_red[kg][j4] = acc;
    }
    __syncthreads();
    if (tid < 32) {
        float4 acc = make_float4(0.f, 0.f, 0.f, 0.f);
#pragma unroll
        for (int g = 0; g < 8; ++g) {
            float4 v = s_red[g][tid];
            acc.x += v.x; acc.y += v.y; acc.z += v.z; acc.w += v.w;
        }
        g_h1p[((size_t)b * 8 + jq) * 32 + tid] = acc;
    }
}

// ---------------------------------------------------------------------------
// K3: per-batch tail: fold h1 partials + b1 -> lrelu -> h2 -> out. R6 body
// behind a PDL grid sync, with pre-sync weight prefetch.
// ---------------------------------------------------------------------------
__global__ void __launch_bounds__(256)
head_kernel(const float4* __restrict__ b14,    // [32] f4
            const float4* __restrict__ wo24,   // [128][32] f4
            const float4* __restrict__ b24,    // [32] f4
            const float4* __restrict__ wo34,   // [128][64] f4
            const float4* __restrict__ b34,    // [64] f4
            float4*       __restrict__ out4)   // [16][64] f4
{
    const int b   = blockIdx.x;
    const int tid = threadIdx.x;

    // pre-sync preamble: warm L2 with tail weights
    {
        prefetch_l2(wo24 + (size_t)tid * 4);
        prefetch_l2(wo34 + (size_t)tid * 8);
        prefetch_l2(wo34 + (size_t)tid * 8 + 1024);
        if (tid < 16) { prefetch_l2(b14 + tid * 2); prefetch_l2(b24 + tid * 2); }
        if (tid < 32) prefetch_l2(b34 + tid * 2);
    }

#if __CUDA_ARCH__ >= 900
    cudaGridDependencySynchronize();
#endif

    __shared__ float4 s_p[256];
    __shared__ float  s_h1[H1];
    __shared__ float  s_h2[H1];

    s_p[tid] = g_h1p[(size_t)b * 256 + tid];
    __syncthreads();

    if (tid < 32) {
        float4 acc = __ldg(&b14[tid]);
#pragma unroll
        for (int g = 0; g < 8; ++g) {
            float4 v = s_p[g * 32 + tid];
            acc.x += v.x; acc.y += v.y; acc.z += v.z; acc.w += v.w;
        }
        s_h1[tid * 4 + 0] = (acc.x > 0.f) ? acc.x : 0.01f * acc.x;
        s_h1[tid * 4 + 1] = (acc.y > 0.f) ? acc.y : 0.01f * acc.y;
        s_h1[tid * 4 + 2] = (acc.z > 0.f) ? acc.z : 0.01f * acc.z;
        s_h1[tid * 4 + 3] = (acc.w > 0.f) ? acc.w : 0.01f * acc.w;
    }
    __syncthreads();

    // h2 = lrelu(h1 @ wo2 + b2): 32 j4 x 8 kg of 16 k
    {
        const int j4 = tid & 31;
        const int kg = tid >> 5;
        const float4* w = wo24 + (size_t)(kg * 16) * 32 + j4;
        const float*  m = s_h1 + kg * 16;
        float4 acc = make_float4(0.f, 0.f, 0.f, 0.f);
#pragma unroll
        for (int k = 0; k < 16; ++k) {
            float4 v = __ldg(&w[(size_t)k * 32]);
            float  s = m[k];
            acc.x += s * v.x; acc.y += s * v.y; acc.z += s * v.z; acc.w += s * v.w;
        }
        __syncthreads();
        s_p[kg * 32 + j4] = acc;
    }
    __syncthreads();
    if (tid < 32) {
        float4 acc = __ldg(&b24[tid]);
#pragma unroll
        for (int g = 0; g < 8; ++g) {
            float4 v = s_p[g * 32 + tid];
            acc.x += v.x; acc.y += v.y; acc.z += v.z; acc.w += v.w;
        }
        s_h2[tid * 4 + 0] = (acc.x > 0.f) ? acc.x : 0.01f * acc.x;
        s_h2[tid * 4 + 1] = (acc.y > 0.f) ? acc.y : 0.01f * acc.y;
        s_h2[tid * 4 + 2] = (acc.z > 0.f) ? acc.z : 0.01f * acc.z;
        s_h2[tid * 4 + 3] = (acc.w > 0.f) ? acc.w : 0.01f * acc.w;
    }
    __syncthreads();

    // out = h2 @ wo3 + b3: 64 j4 x 4 kg of 32 k
    {
        const int j4 = tid & 63;
        const int kg = tid >> 6;
        const float4* w = wo34 + (size_t)(kg * 32) * 64 + j4;
        const float*  m = s_h2 + kg * 32;
        float4 acc = make_float4(0.f, 0.f, 0.f, 0.f);
#pragma unroll 8
        for (int k = 0; k < 32; ++k) {
            float4 v = __ldg(&w[(size_t)k * 64]);
            float  s = m[k];
            acc.x += s * v.x; acc.y += s * v.y; acc.z += s * v.z; acc.w += s * v.w;
        }
        __syncthreads();
        s_p[kg * 64 + j4] = acc;
    }
    __syncthreads();
    if (tid < 64) {
        float4 acc = __ldg(&b34[tid]);
#pragma unroll
        for (int g = 0; g < 4; ++g) {
            float4 v = s_p[g * 64 + tid];
            acc.x += v.x; acc.y += v.y; acc.z += v.z; acc.w += v.w;
        }
        out4[(size_t)b * 64 + tid] = acc;
    }
}

// ---------------------------------------------------------------------------
// Inputs: 0 feature, 1 lidar, 2 conv1_w, 3 conv2_w, 4 wq, 5 wk, 6 wv,
//         7 wo1, 8 b1, 9 wo2, 10 b2, 11 wo3, 12 b3
// ---------------------------------------------------------------------------
extern "C" void kernel_launch(void* const* d_in, const int* in_sizes, int n_in,
                              void* d_out, int out_size)
{
    const float4* lidar4 = (const float4*)d_in[1];
    const float4* wv4    = (const float4*)d_in[6];
    const float4* wo14   = (const float4*)d_in[7];
    const float4* b14    = (const float4*)d_in[8];
    const float4* wo24   = (const float4*)d_in[9];
    const float4* b24    = (const float4*)d_in[10];
    const float4* wo34   = (const float4*)d_in[11];
    const float4* b34    = (const float4*)d_in[12];
    float4* out4 = (float4*)d_out;

    // K1: normal launch
    lidar_reduce_kernel<<<dim3(BATCH, SPLIT), 256>>>(lidar4);

    // K2/K3: programmatic dependent launches (PDL)
    cudaLaunchAttribute pdl[1];
    pdl[0].id = cudaLaunchAttributeProgrammaticStreamSerialization;
    pdl[0].val.programmaticStreamSerializationAllowed = 1;

    {
        cudaLaunchConfig_t cfg = {};
        cfg.gridDim  = dim3(BATCH, 8);
        cfg.blockDim = dim3(256);
        cfg.attrs    = pdl;
        cfg.numAttrs = 1;
        cudaLaunchKernelEx(&cfg, bins_h1_kernel, wv4, wo14);
    }
    {
        cudaLaunchConfig_t cfg = {};
        cfg.gridDim  = dim3(BATCH);
        cfg.blockDim = dim3(256);
        cfg.attrs    = pdl;
        cfg.numAttrs = 1;
        cudaLaunchKernelEx(&cfg, head_kernel, b14, wo24, b24, wo34, b34, out4);
    }
}

// round 15
// speedup vs baseline: 1.1300x; 1.1300x over previous
#include <cuda_runtime.h>

// Live computation: out = MLP( (mean_p lidar[b,p,:]) @ wv ).
// Attention is dead (zero-pad last query row -> uniform softmax -> mean of V).
//
// 3-kernel chain, R6-exact bodies. K2/K3 are PDL (programmatic dependent
// launch) kernels: blocks pre-launch into spare SM slots and HW-wait at
// cudaGridDependencySynchronize() until the predecessor grid completes.
// No prefetch preamble (measured ~0.5us tax in R9/R14), no software spin
// (failed 4x): pure launch-gap elimination.

#define BATCH     16
#define N_POINTS  4096
#define LIDAR_C   256
#define C4        (LIDAR_C / 4)           // 64
#define D_MODEL   1024
#define H1        128
#define SPLIT     64
#define PTS_PER_BLK (N_POINTS / SPLIT)    // 64

__device__ float4 g_partial[SPLIT * BATCH * C4];   // [64][16][64] f4 = 1 MB
__device__ float4 g_h1p[BATCH * 8 * (H1 / 4)];     // [16][8][32] f4

// ---------------------------------------------------------------------------
// K1: partial column sums of lidar (DRAM-bound, 67 MB). R6-exact. FROZEN.
// ---------------------------------------------------------------------------
__global__ void __launch_bounds__(256)
lidar_reduce_kernel(const float4* __restrict__ lidar4)
{
    const int b  = blockIdx.x;
    const int s  = blockIdx.y;
    const int c4 = threadIdx.x & 63;
    const int r  = threadIdx.x >> 6;

    const float4* base = lidar4
        + ((size_t)b * N_POINTS + (size_t)s * PTS_PER_BLK + (size_t)r * 16) * C4 + c4;

    float4 acc = make_float4(0.f, 0.f, 0.f, 0.f);
#pragma unroll
    for (int i = 0; i < 16; ++i) {
        float4 v = __ldcs(&base[(size_t)i * C4]);
        acc.x += v.x; acc.y += v.y; acc.z += v.z; acc.w += v.w;
    }

    __shared__ float4 sp[4][C4];
    sp[r][c4] = acc;
    __syncthreads();

    if (r == 0) {
        float4 a = sp[0][c4], bb = sp[1][c4], c = sp[2][c4], d = sp[3][c4];
        float4 t;
        t.x = (a.x + bb.x) + (c.x + d.x);
        t.y = (a.y + bb.y) + (c.y + d.y);
        t.z = (a.z + bb.z) + (c.z + d.z);
        t.w = (a.w + bb.w) + (c.w + d.w);
        g_partial[((size_t)s * BATCH + b) * C4 + c4] = t;
    }
}

// ---------------------------------------------------------------------------
// K2: per (batch, j-chunk): fold partials -> mean; bins_chunk = mean @ wv
// cols [jq*128,+128); h1 partial = bins_chunk @ wo1[chunk rows]. R6-exact
// body behind a PDL grid sync.
// ---------------------------------------------------------------------------
__global__ void __launch_bounds__(256)
bins_h1_kernel(const float4* __restrict__ wv4,     // [256][256] f4
               const float4* __restrict__ wo14)    // [1024][32] f4
{
#if __CUDA_ARCH__ >= 900
    cudaGridDependencySynchronize();
#endif

    const int b   = blockIdx.x;
    const int jq  = blockIdx.y;                    // 0..7
    const int tid = threadIdx.x;
    const int j4  = tid & 31;
    const int kg  = tid >> 5;                      // 0..7

    __shared__ float4 sp[4][C4];
    __shared__ float  s_mean[LIDAR_C];
    __shared__ float  s_binsc[128];
    __shared__ float4 s_red[8][32];

    // ---- fold 64 partials -> mean -----------------------------------------
    {
        const int c4 = tid & 63;
        const int sg = tid >> 6;                   // 0..3
        const float4* p = g_partial + (size_t)b * C4 + c4;
        float4 acc = make_float4(0.f, 0.f, 0.f, 0.f);
#pragma unroll
        for (int i = 0; i < 16; ++i) {
            float4 v = p[(size_t)(sg * 16 + i) * (BATCH * C4)];
            acc.x += v.x; acc.y += v.y; acc.z += v.z; acc.w += v.w;
        }
        sp[sg][c4] = acc;
    }
    __syncthreads();
    if (tid < C4) {
        float4 a = sp[0][tid], bb = sp[1][tid], c = sp[2][tid], d = sp[3][tid];
        const float inv = 1.0f / (float)N_POINTS;
        s_mean[tid * 4 + 0] = ((a.x + bb.x) + (c.x + d.x)) * inv;
        s_mean[tid * 4 + 1] = ((a.y + bb.y) + (c.y + d.y)) * inv;
        s_mean[tid * 4 + 2] = ((a.z + bb.z) + (c.z + d.z)) * inv;
        s_mean[tid * 4 + 3] = ((a.w + bb.w) + (c.w + d.w)) * inv;
    }
    __syncthreads();

    // ---- bins chunk: 32 j4 x 8 kg of 32 k ----------------------------------
    {
        const float4* w = wv4 + (size_t)(kg * 32) * 256 + jq * 32 + j4;
        const float*  m = s_mean + kg * 32;
        float4 acc = make_float4(0.f, 0.f, 0.f, 0.f);
#pragma unroll 8
        for (int k = 0; k < 32; ++k) {
            float4 v = __ldg(&w[(size_t)k * 256]);
            float  s = m[k];
            acc.x += s * v.x; acc.y += s * v.y; acc.z += s * v.z; acc.w += s * v.w;
        }
        s_red[kg][j4] = acc;
    }
    __syncthreads();
    if (tid < 32) {
        float4 acc = make_float4(0.f, 0.f, 0.f, 0.f);
#pragma unroll
        for (int g = 0; g < 8; ++g) {
            float4 v = s_red[g][tid];
            acc.x += v.x; acc.y += v.y; acc.z += v.z; acc.w += v.w;
        }
        s_binsc[tid * 4 + 0] = acc.x;
        s_binsc[tid * 4 + 1] = acc.y;
        s_binsc[tid * 4 + 2] = acc.z;
        s_binsc[tid * 4 + 3] = acc.w;
    }
    __syncthreads();

    // ---- h1 partial: 32 j4 x 8 kg of 16 k ----------------------------------
    {
        const float4* w = wo14 + ((size_t)jq * 128 + kg * 16) * 32 + j4;
        const float*  m = s_binsc + kg * 16;
        float4 acc = make_float4(0.f, 0.f, 0.f, 0.f);
#pragma unroll
        for (int k = 0; k < 16; ++k) {
            float4 v = __ldg(&w[(size_t)k * 32]);
            float  s = m[k];
            acc.x += s * v.x; acc.y += s * v.y; acc.z += s * v.z; acc.w += s * v.w;
        }
        __syncthreads();
        s_red[kg][j4] = acc;
    }
    __syncthreads();
    if (tid < 32) {
        float4 acc = make_float4(0.f, 0.f, 0.f, 0.f);
#pragma unroll
        for (int g = 0; g < 8; ++g) {
            float4 v = s_red[g][tid];
            acc.x += v.x; acc.y += v.y; acc.z += v.z; acc.w += v.w;
        }
        g_h1p[((size_t)b * 8 + jq) * 32 + tid] = acc;
    }
}

// ---------------------------------------------------------------------------
// K3: per-batch tail: fold h1 partials + b1 -> lrelu -> h2 -> out. R6-exact
// body behind a PDL grid sync.
// ---------------------------------------------------------------------------
__global__ void __launch_bounds__(256)
head_kernel(const float4* __restrict__ b14,    // [32] f4
            const float4* __restrict__ wo24,   // [128][32] f4
            const float4* __restrict__ b24,    // [32] f4
            const float4* __restrict__ wo34,   // [128][64] f4
            const float4* __restrict__ b34,    // [64] f4
            float4*       __restrict__ out4)   // [16][64] f4
{
#if __CUDA_ARCH__ >= 900
    cudaGridDependencySynchronize();
#endif

    const int b   = blockIdx.x;
    const int tid = threadIdx.x;

    __shared__ float4 s_p[256];
    __shared__ float  s_h1[H1];
    __shared__ float  s_h2[H1];

    s_p[tid] = g_h1p[(size_t)b * 256 + tid];
    __syncthreads();

    if (tid < 32) {
        float4 acc = __ldg(&b14[tid]);
#pragma unroll
        for (int g = 0; g < 8; ++g) {
            float4 v = s_p[g * 32 + tid];
            acc.x += v.x; acc.y += v.y; acc.z += v.z; acc.w += v.w;
        }
        s_h1[tid * 4 + 0] = (acc.x > 0.f) ? acc.x : 0.01f * acc.x;
        s_h1[tid * 4 + 1] = (acc.y > 0.f) ? acc.y : 0.01f * acc.y;
        s_h1[tid * 4 + 2] = (acc.z > 0.f) ? acc.z : 0.01f * acc.z;
        s_h1[tid * 4 + 3] = (acc.w > 0.f) ? acc.w : 0.01f * acc.w;
    }
    __syncthreads();

    // h2 = lrelu(h1 @ wo2 + b2): 32 j4 x 8 kg of 16 k
    {
        const int j4 = tid & 31;
        const int kg = tid >> 5;
        const float4* w = wo24 + (size_t)(kg * 16) * 32 + j4;
        const float*  m = s_h1 + kg * 16;
        float4 acc = make_float4(0.f, 0.f, 0.f, 0.f);
#pragma unroll
        for (int k = 0; k < 16; ++k) {
            float4 v = __ldg(&w[(size_t)k * 32]);
            float  s = m[k];
            acc.x += s * v.x; acc.y += s * v.y; acc.z += s * v.z; acc.w += s * v.w;
        }
        __syncthreads();
        s_p[kg * 32 + j4] = acc;
    }
    __syncthreads();
    if (tid < 32) {
        float4 acc = __ldg(&b24[tid]);
#pragma unroll
        for (int g = 0; g < 8; ++g) {
            float4 v = s_p[g * 32 + tid];
            acc.x += v.x; acc.y += v.y; acc.z += v.z; acc.w += v.w;
        }
        s_h2[tid * 4 + 0] = (acc.x > 0.f) ? acc.x : 0.01f * acc.x;
        s_h2[tid * 4 + 1] = (acc.y > 0.f) ? acc.y : 0.01f * acc.y;
        s_h2[tid * 4 + 2] = (acc.z > 0.f) ? acc.z : 0.01f * acc.z;
        s_h2[tid * 4 + 3] = (acc.w > 0.f) ? acc.w : 0.01f * acc.w;
    }
    __syncthreads();

    // out = h2 @ wo3 + b3: 64 j4 x 4 kg of 32 k
    {
        const int j4 = tid & 63;
        const int kg = tid >> 6;
        const float4* w = wo34 + (size_t)(kg * 32) * 64 + j4;
        const float*  m = s_h2 + kg * 32;
        float4 acc = make_float4(0.f, 0.f, 0.f, 0.f);
#pragma unroll 8
        for (int k = 0; k < 32; ++k) {
            float4 v = __ldg(&w[(size_t)k * 64]);
            float  s = m[k];
            acc.x += s * v.x; acc.y += s * v.y; acc.z += s * v.z; acc.w += s * v.w;
        }
        __syncthreads();
        s_p[kg * 64 + j4] = acc;
    }
    __syncthreads();
    if (tid < 64) {
        float4 acc = __ldg(&b34[tid]);
#pragma unroll
        for (int g = 0; g < 4; ++g) {
            float4 v = s_p[g * 64 + tid];
            acc.x += v.x; acc.y += v.y; acc.z += v.z; acc.w += v.w;
        }
        out4[(size_t)b * 64 + tid] = acc;
    }
}

// ---------------------------------------------------------------------------
// Inputs: 0 feature, 1 lidar, 2 conv1_w, 3 conv2_w, 4 wq, 5 wk, 6 wv,
//         7 wo1, 8 b1, 9 wo2, 10 b2, 11 wo3, 12 b3
// ---------------------------------------------------------------------------
extern "C" void kernel_launch(void* const* d_in, const int* in_sizes, int n_in,
                              void* d_out, int out_size)
{
    const float4* lidar4 = (const float4*)d_in[1];
    const float4* wv4    = (const float4*)d_in[6];
    const float4* wo14   = (const float4*)d_in[7];
    const float4* b14    = (const float4*)d_in[8];
    const float4* wo24   = (const float4*)d_in[9];
    const float4* b24    = (const float4*)d_in[10];
    const float4* wo34   = (const float4*)d_in[11];
    const float4* b34    = (const float4*)d_in[12];
    float4* out4 = (float4*)d_out;

    // K1: normal launch
    lidar_reduce_kernel<<<dim3(BATCH, SPLIT), 256>>>(lidar4);

    // K2/K3: programmatic dependent launches (PDL), no preamble work
    cudaLaunchAttribute pdl[1];
    pdl[0].id = cudaLaunchAttributeProgrammaticStreamSerialization;
    pdl[0].val.programmaticStreamSerializationAllowed = 1;

    {
        cudaLaunchConfig_t cfg = {};
        cfg.gridDim  = dim3(BATCH, 8);
        cfg.blockDim = dim3(256);
        cfg.attrs    = pdl;
        cfg.numAttrs = 1;
        cudaLaunchKernelEx(&cfg, bins_h1_kernel, wv4, wo14);
    }
    {
        cudaLaunchConfig_t cfg = {};
        cfg.gridDim  = dim3(BATCH);
        cfg.blockDim = dim3(256);
        cfg.attrs    = pdl;
        cfg.numAttrs = 1;
        cudaLaunchKernelEx(&cfg, head_kernel, b14, wo24, b24, wo34, b34, out4);
    }
}